// round 2
// baseline (speedup 1.0000x reference)
#include <cuda_runtime.h>
#include <cuda_bf16.h>
#include <cstdint>
#include <math.h>

// ============================================================================
// YOLOv3 post-processor (RPN-style): sigmoid -> top-4096 -> decode/clip ->
// greedy NMS (300) -> [16, 300, 6] output (box4 | score | label).
// ============================================================================

namespace yolo {

constexpr int NBATCH = 16, A = 3, H = 160, W = 160, C = 80;
constexpr int P = A * H * W;       // 76800 anchors per image
constexpr int HW = H * W;          // 25600
constexpr int TOPK = 4096;
constexpr int KEEP = 300;
constexpr int NBINS = 8192;        // top 13 bits of monotone score key
constexpr int CAP = 8192;          // candidate capacity per batch
constexpr int NWORD = TOPK / 32;   // 128 alive-mask words
constexpr float XCLIP = 4.135166556742356f;   // log(1000/16)
constexpr float IMGMX = 639.0f;               // 640 - TO_REMOVE

// ---- scratch (device globals: no allocation allowed) ----
__device__ uint32_t            d_hist[NBATCH * NBINS];
__device__ int                 d_thresh[NBATCH];
__device__ int                 d_count[NBATCH];
__device__ unsigned long long  d_cand[NBATCH * CAP];
__device__ unsigned long long  d_sorted[NBATCH * TOPK];
__device__ float4              d_box[NBATCH * TOPK];
__device__ float               d_score[NBATCH * TOPK];
__device__ int                 d_keptP[NBATCH * KEEP];   // sorted-slot of kept box
__device__ int                 d_keptN[NBATCH];

// monotone uint key of sigmoid(logit); sigmoid >= 0 so just set the sign bit
__device__ __forceinline__ uint32_t skey(float logit) {
    float s = 1.0f / (1.0f + expf(-logit));
    return __float_as_uint(s) | 0x80000000u;
}

// ----------------------------------------------------------------------------
__global__ void k_zero() {
    int i = blockIdx.x * blockDim.x + threadIdx.x;
    for (; i < NBATCH * NBINS; i += gridDim.x * blockDim.x) d_hist[i] = 0;
    if (blockIdx.x == 0 && threadIdx.x < NBATCH) d_count[threadIdx.x] = 0;
}

// per-batch histogram of the top 13 key bits; grid (8 chunks, 16 batches)
__global__ void k_hist(const float* __restrict__ obj) {
    __shared__ uint32_t sh[NBINS];
    int n = blockIdx.y;
    for (int i = threadIdx.x; i < NBINS; i += blockDim.x) sh[i] = 0;
    __syncthreads();
    const float* base = obj + (size_t)n * P + (size_t)blockIdx.x * (P / 8);
    for (int i = threadIdx.x; i < P / 8; i += blockDim.x)
        atomicAdd(&sh[skey(base[i]) >> 19], 1u);
    __syncthreads();
    for (int i = threadIdx.x; i < NBINS; i += blockDim.x)
        if (sh[i]) atomicAdd(&d_hist[n * NBINS + i], sh[i]);
}

// find smallest bin T such that count(bins >= T) >= TOPK
__global__ void k_thresh() {
    __shared__ uint32_t part[256];
    int n = blockIdx.x, t = threadIdx.x;
    const uint32_t* h = &d_hist[n * NBINS];
    uint32_t s = 0;
    for (int b = t * 32; b < t * 32 + 32; b++) s += h[b];
    part[t] = s;
    __syncthreads();
    if (t == 0) {
        uint32_t acc = 0;
        int seg = 0;
        for (int pt = 255; pt >= 0; pt--) {
            if (acc + part[pt] >= (uint32_t)TOPK) { seg = pt; break; }
            acc += part[pt];
        }
        int T = seg * 32;
        for (int b = seg * 32 + 31; b >= seg * 32; b--) {
            acc += h[b];
            if (acc >= (uint32_t)TOPK) { T = b; break; }
        }
        d_thresh[n] = T;
    }
}

// compact all elements with bin >= T into per-batch candidate list.
// composite key: (scorebits|sign)<<32 | (P-1-p)  -> desc sort == (score desc, p asc)
// memory index m = a*HW + y*W + x  ->  flattened p = (y*W+x)*A + a
__global__ void k_compact(const float* __restrict__ obj) {
    __shared__ unsigned long long stage[4096];
    __shared__ int scnt, sbase;
    int n = blockIdx.y;
    if (threadIdx.x == 0) scnt = 0;
    __syncthreads();
    int T = d_thresh[n];
    const float* base = obj + (size_t)n * P;
    int m0 = blockIdx.x * (P / 8);
    for (int i = threadIdx.x; i < P / 8; i += blockDim.x) {
        int m = m0 + i;
        uint32_t k = skey(base[m]);
        if ((int)(k >> 19) >= T) {
            int a = m / HW;
            int rem = m - a * HW;            // y*W + x
            int p = rem * A + a;
            int sp = atomicAdd(&scnt, 1);
            if (sp < 4096)
                stage[sp] = ((unsigned long long)k << 32) | (uint32_t)(P - 1 - p);
        }
    }
    __syncthreads();
    if (threadIdx.x == 0) sbase = atomicAdd(&d_count[n], min(scnt, 4096));
    __syncthreads();
    int mm = min(scnt, 4096);
    for (int i = threadIdx.x; i < mm; i += blockDim.x) {
        int dst = sbase + i;
        if (dst < CAP) d_cand[(size_t)n * CAP + dst] = stage[i];
    }
}

// per-batch bitonic sort (descending) of CAP composite keys; keep top TOPK
__global__ __launch_bounds__(1024) void k_sort() {
    extern __shared__ unsigned long long s[];
    int n = blockIdx.x;
    int cnt = min(d_count[n], CAP);
    for (int i = threadIdx.x; i < CAP; i += blockDim.x)
        s[i] = (i < cnt) ? d_cand[(size_t)n * CAP + i] : 0ULL;
    __syncthreads();
    for (int k = 2; k <= CAP; k <<= 1) {
        for (int j = k >> 1; j > 0; j >>= 1) {
            for (int i = threadIdx.x; i < CAP; i += blockDim.x) {
                int ixj = i ^ j;
                if (ixj > i) {
                    unsigned long long a = s[i], b = s[ixj];
                    bool desc = ((i & k) == 0);
                    if ((a < b) == desc) { s[i] = b; s[ixj] = a; }
                }
            }
            __syncthreads();
        }
    }
    for (int i = threadIdx.x; i < TOPK; i += blockDim.x)
        d_sorted[(size_t)n * TOPK + i] = s[i];
}

// decode + clip boxes for the sorted top-4096 of every batch
__global__ void k_decode(const float* __restrict__ anchors,
                         const float* __restrict__ reg) {
    int t = blockIdx.x * blockDim.x + threadIdx.x;
    if (t >= NBATCH * TOPK) return;
    int n = t >> 12;
    unsigned long long e = d_sorted[t];
    int p = P - 1 - (int)(uint32_t)e;
    uint32_t key = (uint32_t)(e >> 32);
    d_score[t] = __uint_as_float(key & 0x7FFFFFFFu);

    int a = p % A;
    int hw = p / A;
    int y = hw / W;
    int x = hw - y * W;
    const float4 anc = *(const float4*)(anchors + ((size_t)n * P + p) * 4);
    float aw = anc.z - anc.x + 1.0f, ah = anc.w - anc.y + 1.0f;
    float acx = anc.x + 0.5f * aw,  acy = anc.y + 0.5f * ah;

    size_t rb = (size_t)((n * A + a) * 4) * HW + (size_t)y * W + x;
    float dx = __ldg(reg + rb);
    float dy = __ldg(reg + rb + HW);
    float dw = fminf(__ldg(reg + rb + 2 * (size_t)HW), XCLIP);
    float dh = fminf(__ldg(reg + rb + 3 * (size_t)HW), XCLIP);

    float pcx = dx * aw + acx, pcy = dy * ah + acy;
    float pw = expf(dw) * aw,  ph = expf(dh) * ah;
    float x1 = pcx - 0.5f * pw, y1 = pcy - 0.5f * ph;
    float x2 = pcx + 0.5f * pw - 1.0f, y2 = pcy + 0.5f * ph - 1.0f;
    x1 = fminf(fmaxf(x1, 0.0f), IMGMX);
    y1 = fminf(fmaxf(y1, 0.0f), IMGMX);
    x2 = fminf(fmaxf(x2, 0.0f), IMGMX);
    y2 = fminf(fmaxf(y2, 0.0f), IMGMX);
    d_box[t] = make_float4(x1, y1, x2, y2);
}

// greedy NMS per batch: sorted order => pointer walk, alive bitmask in shared
__global__ __launch_bounds__(512) void k_nms(float* __restrict__ out) {
    extern __shared__ char smem_raw[];
    float4*   sb      = (float4*)smem_raw;                    // 4096 * 16 B
    float*    sarea   = (float*)(sb + TOPK);                  // 4096 * 4 B
    uint32_t* alive   = (uint32_t*)(sarea + TOPK);            // 128 * 4 B
    int*      keptPos = (int*)(alive + NWORD);                // 300 * 4 B

    int n = blockIdx.x;
    for (int i = threadIdx.x; i < TOPK; i += blockDim.x) {
        float4 b = d_box[(size_t)n * TOPK + i];
        sb[i] = b;
        sarea[i] = (b.z - b.x + 1.0f) * (b.w - b.y + 1.0f);
    }
    for (int i = threadIdx.x; i < NWORD; i += blockDim.x) alive[i] = 0xFFFFFFFFu;
    __syncthreads();

    const int lane = threadIdx.x & 31;
    const int warp = threadIdx.x >> 5;
    const int nwarp = blockDim.x >> 5;
    int ptr = 0, kept = 0;

    while (ptr < TOPK && kept < KEEP) {
        if (threadIdx.x == 0) keptPos[kept] = ptr;
        kept++;
        float4 b = sb[ptr];
        float ba = sarea[ptr];
        for (int c = (ptr >> 5) + warp; c < NWORD; c += nwarp) {
            uint32_t w = alive[c];
            bool sup = false;
            if ((w >> lane) & 1u) {
                int j = (c << 5) + lane;
                float4 q = sb[j];
                float iw = fminf(b.z, q.z) - fmaxf(b.x, q.x) + 1.0f;
                float ih = fminf(b.w, q.w) - fmaxf(b.y, q.y) + 1.0f;
                iw = fmaxf(iw, 0.0f);
                ih = fmaxf(ih, 0.0f);
                float inter = iw * ih;
                sup = inter > 0.5f * (ba + sarea[j] - inter);   // iou > 0.5
            }
            uint32_t msk = __ballot_sync(0xFFFFFFFFu, sup);
            if (lane == 0 && msk) alive[c] = w & ~msk;
        }
        __syncthreads();
        // advance pointer to next alive slot (uniform redundant scan)
        int c = (ptr + 1) >> 5;
        uint32_t m = 0;
        if (c < NWORD) {
            m = alive[c] & (0xFFFFFFFFu << ((ptr + 1) & 31));
            while (m == 0 && ++c < NWORD) m = alive[c];
        }
        ptr = (c < NWORD && m) ? (c << 5) + __ffs(m) - 1 : TOPK;
        __syncthreads();
    }

    // write boxes + scores (+ zero label placeholder); zero invalid rows
    for (int k = threadIdx.x; k < KEEP; k += blockDim.x) {
        float* o = out + (size_t)(n * KEEP + k) * 6;
        if (k < kept) {
            int s = keptPos[k];
            float4 b = sb[s];
            o[0] = b.x; o[1] = b.y; o[2] = b.z; o[3] = b.w;
            o[4] = d_score[(size_t)n * TOPK + s];
            o[5] = 0.0f;
            d_keptP[n * KEEP + k] = s;
        } else {
            o[0] = 0.0f; o[1] = 0.0f; o[2] = 0.0f;
            o[3] = 0.0f; o[4] = 0.0f; o[5] = 0.0f;
        }
    }
    if (threadIdx.x == 0) d_keptN[n] = kept;
}

// one warp per kept row: argmax over C=80 class logits, label = argmax + 1
__global__ void k_labels(const float* __restrict__ cls, float* __restrict__ out) {
    int warp_g = (blockIdx.x * blockDim.x + threadIdx.x) >> 5;
    int lane = threadIdx.x & 31;
    int nwarps = (gridDim.x * blockDim.x) >> 5;
    for (int r = warp_g; r < NBATCH * KEEP; r += nwarps) {
        int n = r / KEEP, k = r - n * KEEP;
        if (k >= d_keptN[n]) continue;
        int s = d_keptP[n * KEEP + k];
        unsigned long long e = d_sorted[(size_t)n * TOPK + s];
        int p = P - 1 - (int)(uint32_t)e;
        int a = p % A;
        int hw = p / A;
        int y = hw / W;
        int x = hw - y * W;
        size_t base = (size_t)((n * A + a) * C) * HW + (size_t)y * W + x;
        float best = -INFINITY;
        int bc = 0;
        for (int c = lane; c < C; c += 32) {
            float v = __ldg(cls + base + (size_t)c * HW);
            if (v > best) { best = v; bc = c; }
        }
        #pragma unroll
        for (int off = 16; off; off >>= 1) {
            float ov = __shfl_xor_sync(0xFFFFFFFFu, best, off);
            int   oc = __shfl_xor_sync(0xFFFFFFFFu, bc, off);
            if (ov > best || (ov == best && oc < bc)) { best = ov; bc = oc; }
        }
        if (lane == 0) out[(size_t)r * 6 + 5] = (float)(bc + 1);
    }
}

}  // namespace yolo

// ============================================================================
extern "C" void kernel_launch(void* const* d_in, const int* in_sizes, int n_in,
                              void* d_out, int out_size) {
    using namespace yolo;
    const float* anchors = (const float*)d_in[0];   // [16, 76800, 4]
    const float* obj     = (const float*)d_in[1];   // [16, 3, 160, 160]
    const float* reg     = (const float*)d_in[2];   // [16, 12, 160, 160]
    const float* cls     = (const float*)d_in[3];   // [16, 240, 160, 160]
    float* out = (float*)d_out;                     // [16, 300, 6]

    static bool attr_done = false;
    if (!attr_done) {
        cudaFuncSetAttribute(k_sort, cudaFuncAttributeMaxDynamicSharedMemorySize,
                             CAP * (int)sizeof(unsigned long long));
        cudaFuncSetAttribute(k_nms, cudaFuncAttributeMaxDynamicSharedMemorySize,
                             TOPK * 16 + TOPK * 4 + NWORD * 4 + KEEP * 4);
        attr_done = true;
    }

    k_zero<<<64, 256>>>();
    k_hist<<<dim3(8, NBATCH), 512>>>(obj);
    k_thresh<<<NBATCH, 256>>>();
    k_compact<<<dim3(8, NBATCH), 512>>>(obj);
    k_sort<<<NBATCH, 1024, CAP * sizeof(unsigned long long)>>>();
    k_decode<<<(NBATCH * TOPK + 255) / 256, 256>>>(anchors, reg);
    k_nms<<<NBATCH, 512, TOPK * 16 + TOPK * 4 + NWORD * 4 + KEEP * 4>>>(out);
    k_labels<<<80, 256>>>(cls, out);
}

// round 3
// speedup vs baseline: 1.5050x; 1.5050x over previous
#include <cuda_runtime.h>
#include <cuda_bf16.h>
#include <cstdint>
#include <math.h>

// ============================================================================
// YOLOv3 post-processor: sigmoid -> top-4096 -> decode/clip -> greedy NMS(300)
// -> [16, 300, 6] (box4 | score | label)
// ============================================================================

namespace yolo {

constexpr int NBATCH = 16, A = 3, H = 160, W = 160, C = 80;
constexpr int P = A * H * W;       // 76800
constexpr int HW = H * W;          // 25600
constexpr int TOPK = 4096;
constexpr int KEEP = 300;
constexpr int NBINS = 8192;        // top 13 bits of monotone score key
constexpr int CAP = 8192;
constexpr float XCLIP = 4.135166556742356f;   // log(1000/16)
constexpr float IMGMX = 639.0f;               // 640 - TO_REMOVE

typedef unsigned long long u64;

// ---- scratch ----
__device__ uint32_t d_keys[NBATCH * P];
__device__ uint32_t d_hist[NBATCH * NBINS];
__device__ int      d_thresh[NBATCH];
__device__ int      d_count[NBATCH];
__device__ u64      d_cand[NBATCH * CAP];
__device__ u64      d_sorted[NBATCH * TOPK];
__device__ float4   d_box[NBATCH * TOPK];
__device__ float    d_score[NBATCH * TOPK];
__device__ int      d_keptP[NBATCH * KEEP];
__device__ int      d_keptN[NBATCH];

// monotone uint key of sigmoid(logit); sigmoid >= 0 so set the sign bit
__device__ __forceinline__ uint32_t skey(float logit) {
    float s = 1.0f / (1.0f + expf(-logit));
    return __float_as_uint(s) | 0x80000000u;
}

// ----------------------------------------------------------------------------
__global__ void k_zero() {
    int i = blockIdx.x * blockDim.x + threadIdx.x;
    for (; i < NBATCH * NBINS; i += gridDim.x * blockDim.x) d_hist[i] = 0;
    if (blockIdx.x == 0 && threadIdx.x < NBATCH) d_count[threadIdx.x] = 0;
}

// compute keys once (store), histogram top-13 key bits. grid (8, 16) x 512
__global__ void k_keys(const float* __restrict__ obj) {
    __shared__ uint32_t sh[NBINS];
    int n = blockIdx.y;
    for (int i = threadIdx.x; i < NBINS; i += blockDim.x) sh[i] = 0;
    __syncthreads();
    size_t off = (size_t)n * P + (size_t)blockIdx.x * (P / 8);
    const float* base = obj + off;
    uint32_t* kbase = d_keys + off;
    for (int i = threadIdx.x; i < P / 8; i += blockDim.x) {
        uint32_t k = skey(base[i]);
        kbase[i] = k;
        atomicAdd(&sh[k >> 19], 1u);
    }
    __syncthreads();
    for (int i = threadIdx.x; i < NBINS; i += blockDim.x)
        if (sh[i]) atomicAdd(&d_hist[n * NBINS + i], sh[i]);
}

// smallest bin T such that count(bins >= T) >= TOPK
__global__ void k_thresh() {
    __shared__ uint32_t part[256];
    int n = blockIdx.x, t = threadIdx.x;
    const uint32_t* h = &d_hist[n * NBINS];
    uint32_t s = 0;
    for (int b = t * 32; b < t * 32 + 32; b++) s += h[b];
    part[t] = s;
    __syncthreads();
    if (t == 0) {
        uint32_t acc = 0;
        int seg = 0;
        for (int pt = 255; pt >= 0; pt--) {
            if (acc + part[pt] >= (uint32_t)TOPK) { seg = pt; break; }
            acc += part[pt];
        }
        int T = seg * 32;
        for (int b = seg * 32 + 31; b >= seg * 32; b--) {
            acc += h[b];
            if (acc >= (uint32_t)TOPK) { T = b; break; }
        }
        d_thresh[n] = T;
    }
}

// compact keys >= threshold; warp-aggregated atomics, direct scattered stores.
// composite key: key<<32 | (P-1-p) -> desc sort == (score desc, p asc)
// memory m = a*HW + y*W + x  ->  flattened p = (y*W+x)*A + a
__global__ void k_compact() {
    int n = blockIdx.y;
    int T = d_thresh[n];
    const uint32_t* kbase = d_keys + (size_t)n * P;
    int m0 = blockIdx.x * (P / 8);
    const int CH = P / 8;                       // 9600
    const int iters = (CH + 511) / 512;         // 19
    int lane = threadIdx.x & 31;
    for (int it = 0; it < iters; it++) {
        int i = it * 512 + threadIdx.x;
        bool sel = false;
        uint32_t key = 0;
        int p = 0;
        if (i < CH) {
            int m = m0 + i;
            key = kbase[m];
            sel = (int)(key >> 19) >= T;
            int a = m / HW;
            int rem = m - a * HW;
            p = rem * A + a;
        }
        unsigned msk = __ballot_sync(0xFFFFFFFFu, sel);
        if (msk) {
            int leader = __ffs(msk) - 1;
            unsigned base = 0;
            if (lane == leader) base = atomicAdd(&d_count[n], __popc(msk));
            base = __shfl_sync(0xFFFFFFFFu, base, leader);
            if (sel) {
                unsigned pos = base + __popc(msk & ((1u << lane) - 1));
                if (pos < CAP)
                    d_cand[(size_t)n * CAP + pos] =
                        ((u64)key << 32) | (uint32_t)(P - 1 - p);
            }
        }
    }
}

// ----------------------------------------------------------------------------
#define CSWAP(x, y, d) { if (((x) < (y)) == (d)) { u64 _t = (x); (x) = (y); (y) = _t; } }

// per-batch register-assisted bitonic sort (descending) of CAP keys
__global__ __launch_bounds__(1024) void k_sort() {
    extern __shared__ u64 s[];
    int n = blockIdx.x;
    int cnt = min(d_count[n], CAP);
    for (int i = threadIdx.x; i < CAP; i += blockDim.x)
        s[i] = (i < cnt) ? d_cand[(size_t)n * CAP + i] : 0ULL;
    __syncthreads();

    const unsigned g0 = threadIdx.x * 8u;
    u64 r[8];

    // initial k=2,4,8 entirely in registers
    {
        #pragma unroll
        for (int e = 0; e < 8; e++) r[e] = s[g0 + e];
        // k=2, j=1
        CSWAP(r[0], r[1], true);  CSWAP(r[2], r[3], false);
        CSWAP(r[4], r[5], true);  CSWAP(r[6], r[7], false);
        // k=4, j=2
        CSWAP(r[0], r[2], true);  CSWAP(r[1], r[3], true);
        CSWAP(r[4], r[6], false); CSWAP(r[5], r[7], false);
        // k=4, j=1
        CSWAP(r[0], r[1], true);  CSWAP(r[2], r[3], true);
        CSWAP(r[4], r[5], false); CSWAP(r[6], r[7], false);
        // k=8, j=4,2,1 ; dir by bit3 of g0 (= parity of tid)
        bool d8 = ((g0 & 8u) == 0u);
        CSWAP(r[0], r[4], d8); CSWAP(r[1], r[5], d8);
        CSWAP(r[2], r[6], d8); CSWAP(r[3], r[7], d8);
        CSWAP(r[0], r[2], d8); CSWAP(r[1], r[3], d8);
        CSWAP(r[4], r[6], d8); CSWAP(r[5], r[7], d8);
        CSWAP(r[0], r[1], d8); CSWAP(r[2], r[3], d8);
        CSWAP(r[4], r[5], d8); CSWAP(r[6], r[7], d8);
        #pragma unroll
        for (int e = 0; e < 8; e++) s[g0 + e] = r[e];
    }
    __syncthreads();

    for (unsigned k = 16; k <= (unsigned)CAP; k <<= 1) {
        for (unsigned j = k >> 1; j >= 8; j >>= 1) {
            // exact pair enumeration: CAP/2 pairs over 1024 threads
            for (unsigned q = threadIdx.x; q < CAP / 2; q += 1024) {
                unsigned low = q & (j - 1);
                unsigned i = ((q ^ low) << 1) | low;   // bit j cleared
                unsigned ix = i | j;
                u64 a = s[i], b = s[ix];
                bool desc = ((i & k) == 0);
                if ((a < b) == desc) { s[i] = b; s[ix] = a; }
            }
            __syncthreads();
        }
        // local j=4,2,1 in registers; direction uniform across 8 (k >= 16)
        {
            #pragma unroll
            for (int e = 0; e < 8; e++) r[e] = s[g0 + e];
            bool d = ((g0 & k) == 0);
            CSWAP(r[0], r[4], d); CSWAP(r[1], r[5], d);
            CSWAP(r[2], r[6], d); CSWAP(r[3], r[7], d);
            CSWAP(r[0], r[2], d); CSWAP(r[1], r[3], d);
            CSWAP(r[4], r[6], d); CSWAP(r[5], r[7], d);
            CSWAP(r[0], r[1], d); CSWAP(r[2], r[3], d);
            CSWAP(r[4], r[5], d); CSWAP(r[6], r[7], d);
            #pragma unroll
            for (int e = 0; e < 8; e++) s[g0 + e] = r[e];
        }
        __syncthreads();
    }

    for (int i = threadIdx.x; i < TOPK; i += blockDim.x)
        d_sorted[(size_t)n * TOPK + i] = s[i];
}

// decode + clip the sorted top-4096
__global__ void k_decode(const float* __restrict__ anchors,
                         const float* __restrict__ reg) {
    int t = blockIdx.x * blockDim.x + threadIdx.x;
    if (t >= NBATCH * TOPK) return;
    int n = t >> 12;
    u64 e = d_sorted[t];
    int p = P - 1 - (int)(uint32_t)e;
    uint32_t key = (uint32_t)(e >> 32);
    d_score[t] = __uint_as_float(key & 0x7FFFFFFFu);

    int a = p % A;
    int hw = p / A;
    int y = hw / W;
    int x = hw - y * W;
    const float4 anc = *(const float4*)(anchors + ((size_t)n * P + p) * 4);
    float aw = anc.z - anc.x + 1.0f, ah = anc.w - anc.y + 1.0f;
    float acx = anc.x + 0.5f * aw,  acy = anc.y + 0.5f * ah;

    size_t rb = (size_t)((n * A + a) * 4) * HW + (size_t)y * W + x;
    float dx = __ldg(reg + rb);
    float dy = __ldg(reg + rb + HW);
    float dw = fminf(__ldg(reg + rb + 2 * (size_t)HW), XCLIP);
    float dh = fminf(__ldg(reg + rb + 3 * (size_t)HW), XCLIP);

    float pcx = dx * aw + acx, pcy = dy * ah + acy;
    float pw = expf(dw) * aw,  ph = expf(dh) * ah;
    float x1 = pcx - 0.5f * pw, y1 = pcy - 0.5f * ph;
    float x2 = pcx + 0.5f * pw - 1.0f, y2 = pcy + 0.5f * ph - 1.0f;
    x1 = fminf(fmaxf(x1, 0.0f), IMGMX);
    y1 = fminf(fmaxf(y1, 0.0f), IMGMX);
    x2 = fminf(fmaxf(x2, 0.0f), IMGMX);
    y2 = fminf(fmaxf(y2, 0.0f), IMGMX);
    d_box[t] = make_float4(x1, y1, x2, y2);
}

// ----------------------------------------------------------------------------
// Register-resident greedy NMS: each of 512 threads owns 8 boxes + alive mask.
// Per pick: 8 reg IoU tests, redux-min for next alive pointer, 2 barriers.
__global__ __launch_bounds__(512) void k_nms(float* __restrict__ out) {
    extern __shared__ float dsm[];
    float* sx1 = dsm;
    float* sy1 = sx1 + TOPK;
    float* sx2 = sy1 + TOPK;
    float* sy2 = sx2 + TOPK;
    float* sar = sy2 + TOPK;
    unsigned* swmin = (unsigned*)(sar + TOPK);   // 16
    int* keptPos = (int*)(swmin + 16);           // KEEP

    int n = blockIdx.x;
    int tid = threadIdx.x;
    int lane = tid & 31, warp = tid >> 5;

    for (int i = tid; i < TOPK; i += 512) {
        float4 b = d_box[(size_t)n * TOPK + i];
        sx1[i] = b.x; sy1[i] = b.y; sx2[i] = b.z; sy2[i] = b.w;
        sar[i] = (b.z - b.x + 1.0f) * (b.w - b.y + 1.0f);
    }
    __syncthreads();

    const int g0 = tid * 8;
    float rx1[8], ry1[8], rx2[8], ry2[8], rar[8];
    #pragma unroll
    for (int e = 0; e < 8; e++) {
        rx1[e] = sx1[g0 + e]; ry1[e] = sy1[g0 + e];
        rx2[e] = sx2[g0 + e]; ry2[e] = sy2[g0 + e];
        rar[e] = sar[g0 + e];
    }

    unsigned aliveMask = 0xFFu;
    unsigned ptr = 0;
    int kept = 0;

    while (ptr < (unsigned)TOPK && kept < KEEP) {
        if (tid == 0) keptPos[kept] = (int)ptr;
        kept++;
        float px1 = sx1[ptr], py1 = sy1[ptr];
        float px2 = sx2[ptr], py2 = sy2[ptr], pa = sar[ptr];
        #pragma unroll
        for (int e = 0; e < 8; e++) {
            if ((aliveMask >> e) & 1u) {
                float iw = fminf(px2, rx2[e]) - fmaxf(px1, rx1[e]) + 1.0f;
                float ih = fminf(py2, ry2[e]) - fmaxf(py1, ry1[e]) + 1.0f;
                iw = fmaxf(iw, 0.0f);
                ih = fmaxf(ih, 0.0f);
                float inter = iw * ih;
                if (inter > 0.5f * (pa + rar[e] - inter))
                    aliveMask &= ~(1u << e);
            }
        }
        unsigned cand = aliveMask ? (unsigned)(g0 + __ffs(aliveMask) - 1)
                                  : 0xFFFFFFFFu;
        unsigned wmin = __reduce_min_sync(0xFFFFFFFFu, cand);
        if (lane == 0) swmin[warp] = wmin;
        __syncthreads();
        unsigned mn = swmin[0];
        #pragma unroll
        for (int w = 1; w < 16; w++) mn = min(mn, swmin[w]);
        ptr = mn;
        __syncthreads();   // protect swmin before next round's writes
    }

    // output boxes + scores (+ zero label placeholder); zero invalid rows
    for (int k = tid; k < KEEP; k += 512) {
        float* o = out + (size_t)(n * KEEP + k) * 6;
        if (k < kept) {
            int sidx = keptPos[k];
            o[0] = sx1[sidx]; o[1] = sy1[sidx];
            o[2] = sx2[sidx]; o[3] = sy2[sidx];
            o[4] = d_score[(size_t)n * TOPK + sidx];
            o[5] = 0.0f;
            d_keptP[n * KEEP + k] = sidx;
        } else {
            o[0] = 0.0f; o[1] = 0.0f; o[2] = 0.0f;
            o[3] = 0.0f; o[4] = 0.0f; o[5] = 0.0f;
        }
    }
    if (tid == 0) d_keptN[n] = kept;
}

// one warp per kept row: argmax over C=80 class logits, label = argmax + 1
__global__ void k_labels(const float* __restrict__ cls, float* __restrict__ out) {
    int warp_g = (blockIdx.x * blockDim.x + threadIdx.x) >> 5;
    int lane = threadIdx.x & 31;
    int nwarps = (gridDim.x * blockDim.x) >> 5;
    for (int r = warp_g; r < NBATCH * KEEP; r += nwarps) {
        int n = r / KEEP, k = r - n * KEEP;
        if (k >= d_keptN[n]) continue;
        int s = d_keptP[n * KEEP + k];
        u64 e = d_sorted[(size_t)n * TOPK + s];
        int p = P - 1 - (int)(uint32_t)e;
        int a = p % A;
        int hw = p / A;
        int y = hw / W;
        int x = hw - y * W;
        size_t base = (size_t)((n * A + a) * C) * HW + (size_t)y * W + x;
        float best = -INFINITY;
        int bc = 0;
        for (int c = lane; c < C; c += 32) {
            float v = __ldg(cls + base + (size_t)c * HW);
            if (v > best) { best = v; bc = c; }
        }
        #pragma unroll
        for (int off = 16; off; off >>= 1) {
            float ov = __shfl_xor_sync(0xFFFFFFFFu, best, off);
            int   oc = __shfl_xor_sync(0xFFFFFFFFu, bc, off);
            if (ov > best || (ov == best && oc < bc)) { best = ov; bc = oc; }
        }
        if (lane == 0) out[(size_t)r * 6 + 5] = (float)(bc + 1);
    }
}

}  // namespace yolo

// ============================================================================
extern "C" void kernel_launch(void* const* d_in, const int* in_sizes, int n_in,
                              void* d_out, int out_size) {
    using namespace yolo;
    const float* anchors = (const float*)d_in[0];   // [16, 76800, 4]
    const float* obj     = (const float*)d_in[1];   // [16, 3, 160, 160]
    const float* reg     = (const float*)d_in[2];   // [16, 12, 160, 160]
    const float* cls     = (const float*)d_in[3];   // [16, 240, 160, 160]
    float* out = (float*)d_out;                     // [16, 300, 6]

    const int SORT_SMEM = CAP * (int)sizeof(u64);                    // 64 KB
    const int NMS_SMEM = TOPK * 5 * 4 + 16 * 4 + KEEP * 4;           // ~83 KB

    static bool attr_done = false;
    if (!attr_done) {
        cudaFuncSetAttribute(k_sort, cudaFuncAttributeMaxDynamicSharedMemorySize,
                             SORT_SMEM);
        cudaFuncSetAttribute(k_nms, cudaFuncAttributeMaxDynamicSharedMemorySize,
                             NMS_SMEM);
        attr_done = true;
    }

    k_zero<<<64, 256>>>();
    k_keys<<<dim3(8, NBATCH), 512>>>(obj);
    k_thresh<<<NBATCH, 256>>>();
    k_compact<<<dim3(8, NBATCH), 512>>>();
    k_sort<<<NBATCH, 1024, SORT_SMEM>>>();
    k_decode<<<(NBATCH * TOPK + 255) / 256, 256>>>(anchors, reg);
    k_nms<<<NBATCH, 512, NMS_SMEM>>>(out);
    k_labels<<<80, 256>>>(cls, out);
}